// round 2
// baseline (speedup 1.0000x reference)
#include <cuda_runtime.h>

// Shapes fixed by the dataset
#define CC  64      // classes
#define AA  256     // feature dim
#define CSPLIT 4    // c-slices per y  -> grid 4*64 = 256 blocks
#define CB  16      // classes per block
#define NT  128     // threads per block (4 warps)
#define TR  8       // a-rows per G tile

// Fixed-slot scratch (deterministic, no allocation, no atomics)
__device__ float g_S[CC * CC];        // S[y][c]
__device__ float g_blockSums[1024];
__device__ int   g_lab64;

// ---------------------------------------------------------------------------
// Labels may be int32 (JAX default) or int64 (x64). Range-check the first 8
// int64 interpretations: int32 data aliases high words and blows the range.
// ---------------------------------------------------------------------------
__global__ void k_detect(const long long* __restrict__ labels) {
    int ok = 1;
#pragma unroll
    for (int i = 0; i < 8; i++) {
        long long v = labels[i];
        if (v < 0 || v >= CC) ok = 0;
    }
    g_lab64 = ok;
}

// ---------------------------------------------------------------------------
// S[y,c] = (w_c - w_y)^T G_y (w_c - w_y).  Block (cslice q, y) handles 16 c's.
// Warp w owns c = q*16 + w*4 + {0..3}; lane owns b-cols {lane*4..+3, 128+lane*4..+3}.
// G_y streamed through a double-buffered 8-row smem tile (register prefetch).
// ---------------------------------------------------------------------------
__global__ __launch_bounds__(NT) void k_quad(
        const float* __restrict__ W, const float* __restrict__ CV) {
    __shared__ float Dq[CB][AA];       // 16 KB: D rows for this block's c's
    __shared__ float Gt[2][TR * AA];   // 2 x 8 KB tile double buffer

    const int y    = blockIdx.y;
    const int q    = blockIdx.x;
    const int tid  = threadIdx.x;
    const int w    = tid >> 5;
    const int lane = tid & 31;

    // Build Dq = W[q*16 + r][:] - W[y][:]   (vectorized, coalesced)
    const float* wy = W + y * AA;
    for (int idx = tid; idx < CB * (AA / 4); idx += NT) {
        const int r  = idx >> 6;           // / (AA/4)
        const int a4 = (idx & 63) << 2;
        float4 wv = *(const float4*)(W + (q * CB + r) * AA + a4);
        float4 yv = *(const float4*)(wy + a4);
        float4 d;
        d.x = wv.x - yv.x; d.y = wv.y - yv.y;
        d.z = wv.z - yv.z; d.w = wv.w - yv.w;
        *(float4*)(&Dq[r][a4]) = d;
    }

    const float* G = CV + (size_t)y * (AA * AA);

    // Prologue: tile 0 -> buffer 0 (TR*AA = 2048 floats; 4 float4 per thread)
    float4 pf0, pf1, pf2, pf3;
    pf0 = *(const float4*)(G + (0 * NT + tid) * 4);
    pf1 = *(const float4*)(G + (1 * NT + tid) * 4);
    pf2 = *(const float4*)(G + (2 * NT + tid) * 4);
    pf3 = *(const float4*)(G + (3 * NT + tid) * 4);
    *(float4*)(&Gt[0][(0 * NT + tid) * 4]) = pf0;
    *(float4*)(&Gt[0][(1 * NT + tid) * 4]) = pf1;
    *(float4*)(&Gt[0][(2 * NT + tid) * 4]) = pf2;
    *(float4*)(&Gt[0][(3 * NT + tid) * 4]) = pf3;
    __syncthreads();

    const int c0 = w * 4;   // Dq row base for this warp
    float acc[4][8];
#pragma unroll
    for (int ci = 0; ci < 4; ci++)
#pragma unroll
        for (int k = 0; k < 8; k++) acc[ci][k] = 0.f;

    const int b0 = lane * 4;          // first 4 b-cols
    const int b1 = 128 + lane * 4;    // second 4 b-cols

#pragma unroll 1
    for (int t = 0; t < AA / TR; t++) {
        if (t + 1 < AA / TR) {        // prefetch next tile to registers
            const float* Gn = G + (size_t)(t + 1) * (TR * AA);
            pf0 = *(const float4*)(Gn + (0 * NT + tid) * 4);
            pf1 = *(const float4*)(Gn + (1 * NT + tid) * 4);
            pf2 = *(const float4*)(Gn + (2 * NT + tid) * 4);
            pf3 = *(const float4*)(Gn + (3 * NT + tid) * 4);
        }
        const float* buf = Gt[t & 1];
        const int abase = t * TR;
#pragma unroll
        for (int rr = 0; rr < TR; rr += 4) {
            float4 u[4];
#pragma unroll
            for (int ci = 0; ci < 4; ci++)     // warp-broadcast loads
                u[ci] = *(const float4*)(&Dq[c0 + ci][abase + rr]);
#pragma unroll
            for (int e = 0; e < 4; e++) {
                const int r = rr + e;
                float4 g0 = *(const float4*)(buf + r * AA + b0);
                float4 g1 = *(const float4*)(buf + r * AA + b1);
#pragma unroll
                for (int ci = 0; ci < 4; ci++) {
                    const float uu = (e == 0) ? u[ci].x :
                                     (e == 1) ? u[ci].y :
                                     (e == 2) ? u[ci].z : u[ci].w;
                    acc[ci][0] = fmaf(uu, g0.x, acc[ci][0]);
                    acc[ci][1] = fmaf(uu, g0.y, acc[ci][1]);
                    acc[ci][2] = fmaf(uu, g0.z, acc[ci][2]);
                    acc[ci][3] = fmaf(uu, g0.w, acc[ci][3]);
                    acc[ci][4] = fmaf(uu, g1.x, acc[ci][4]);
                    acc[ci][5] = fmaf(uu, g1.y, acc[ci][5]);
                    acc[ci][6] = fmaf(uu, g1.z, acc[ci][6]);
                    acc[ci][7] = fmaf(uu, g1.w, acc[ci][7]);
                }
            }
        }
        if (t + 1 < AA / TR) {
            __syncthreads();   // all readers done with the buffer we overwrite
            float* nbuf = Gt[(t + 1) & 1];
            *(float4*)(&nbuf[(0 * NT + tid) * 4]) = pf0;
            *(float4*)(&nbuf[(1 * NT + tid) * 4]) = pf1;
            *(float4*)(&nbuf[(2 * NT + tid) * 4]) = pf2;
            *(float4*)(&nbuf[(3 * NT + tid) * 4]) = pf3;
            __syncthreads();
        }
    }

    // Epilogue: S = sum_b t[c,b] * D[c,b]; warp-reduce, lane 0 writes
#pragma unroll
    for (int ci = 0; ci < 4; ci++) {
        float4 d0 = *(const float4*)(&Dq[c0 + ci][b0]);
        float4 d1 = *(const float4*)(&Dq[c0 + ci][b1]);
        float p = acc[ci][0] * d0.x + acc[ci][1] * d0.y
                + acc[ci][2] * d0.z + acc[ci][3] * d0.w
                + acc[ci][4] * d1.x + acc[ci][5] * d1.y
                + acc[ci][6] * d1.z + acc[ci][7] * d1.w;
#pragma unroll
        for (int off = 16; off; off >>= 1)
            p += __shfl_xor_sync(0xffffffffu, p, off);
        if (lane == 0)
            g_S[y * CC + q * CB + c0 + ci] = p;
    }
}

// ---------------------------------------------------------------------------
// Per-row softmax cross-entropy. One warp per row (C=64 -> 2 vals per lane).
// ---------------------------------------------------------------------------
__global__ __launch_bounds__(256) void k_loss(
        const float* __restrict__ pred, const void* __restrict__ labels,
        const float* __restrict__ Lam, int n_total) {
    const int w    = threadIdx.x >> 5;
    const int lane = threadIdx.x & 31;
    const int n    = blockIdx.x * 8 + w;
    __shared__ float ws[8];

    float nll = 0.f;
    if (n < n_total) {
        const int y = g_lab64 ? (int)((const long long*)labels)[n]
                              : ((const int*)labels)[n];
        const float lam = 0.5f * __ldg(Lam);
        const float* p = pred + (size_t)n * CC;
        const int c2 = lane + 32;

        float a1 = p[lane] + lam * g_S[y * CC + lane];
        float a2 = p[c2]   + lam * g_S[y * CC + c2];

        float m = fmaxf(a1, a2);
#pragma unroll
        for (int off = 16; off; off >>= 1)
            m = fmaxf(m, __shfl_xor_sync(0xffffffffu, m, off));
        float e = __expf(a1 - m) + __expf(a2 - m);
#pragma unroll
        for (int off = 16; off; off >>= 1)
            e += __shfl_xor_sync(0xffffffffu, e, off);
        float ay = (lane == y) ? a1 : ((c2 == y) ? a2 : -3.4e38f);
#pragma unroll
        for (int off = 16; off; off >>= 1)
            ay = fmaxf(ay, __shfl_xor_sync(0xffffffffu, ay, off));
        nll = m + __logf(e) - ay;
    }
    if (lane == 0) ws[w] = nll;
    __syncthreads();
    if (threadIdx.x == 0) {
        float s = 0.f;
#pragma unroll
        for (int i = 0; i < 8; i++) s += ws[i];
        g_blockSums[blockIdx.x] = s;
    }
}

// ---------------------------------------------------------------------------
// Final mean
// ---------------------------------------------------------------------------
__global__ __launch_bounds__(512) void k_final(
        float* __restrict__ out, int nblocks, int n_total) {
    __shared__ float ws[16];
    float v = 0.f;
    for (int i = threadIdx.x; i < nblocks; i += 512)
        v += g_blockSums[i];
#pragma unroll
    for (int off = 16; off; off >>= 1)
        v += __shfl_xor_sync(0xffffffffu, v, off);
    if ((threadIdx.x & 31) == 0) ws[threadIdx.x >> 5] = v;
    __syncthreads();
    if (threadIdx.x == 0) {
        float s = 0.f;
#pragma unroll
        for (int i = 0; i < 16; i++) s += ws[i];
        out[0] = s / (float)n_total;
    }
}

// ---------------------------------------------------------------------------
// Inputs (metadata order): fc_weight[C,A] f32, features (unused), pred[N,C] f32,
// labels[N] i32/i64, Lambda[1] f32, covariance_sample[C,A,A] f32.
// ---------------------------------------------------------------------------
extern "C" void kernel_launch(void* const* d_in, const int* in_sizes, int n_in,
                              void* d_out, int out_size) {
    const float* W      = (const float*)d_in[0];
    const float* pred   = (const float*)d_in[2];
    const void*  labels = d_in[3];
    const float* Lam    = (const float*)d_in[4];
    const float* CV     = (const float*)d_in[5];
    const int n_total   = in_sizes[2] / CC;   // 4096

    k_detect<<<1, 1>>>((const long long*)labels);
    k_quad<<<dim3(CSPLIT, CC), NT>>>(W, CV);
    const int nb = (n_total + 7) / 8;         // 512
    k_loss<<<nb, 256>>>(pred, labels, Lam, n_total);
    k_final<<<1, 512>>>((float*)d_out, nb, n_total);
}

// round 3
// speedup vs baseline: 1.0125x; 1.0125x over previous
#include <cuda_runtime.h>

// Shapes fixed by the dataset
#define CC  64      // classes
#define AA  256     // feature dim
#define CSPLIT 4    // c-slices per y  -> grid 4*64 = 256 blocks
#define CB  16      // classes per block
#define NT  128     // threads per block (4 warps)
#define TR  8       // a-rows per G tile

#define LOSS_NB 64  // k_loss blocks (512 threads each; warp = 4 rows)

// Fixed-slot scratch (deterministic, no allocation)
__device__ float g_S[CC * CC];        // S[y][c]
__device__ float g_blockSums[LOSS_NB];
__device__ int   g_count = 0;         // last-block-done counter (self-resetting)
__device__ int   g_lab64;

// ---------------------------------------------------------------------------
// S[y,c] = (w_c - w_y)^T G_y (w_c - w_y).  Block (cslice q, y) handles 16 c's.
// Warp w owns c = q*16 + w*4 + {0..3}; lane owns b-cols {lane*4..+3, 128+lane*4..+3}.
// G_y streamed through a double-buffered 8-row smem tile (register prefetch).
// Block (0,0) thread 0 additionally detects the labels dtype (i32 vs i64).
// ---------------------------------------------------------------------------
__global__ __launch_bounds__(NT) void k_quad(
        const float* __restrict__ W, const float* __restrict__ CV,
        const long long* __restrict__ labels) {
    __shared__ float Dq[CB][AA];       // 16 KB: D rows for this block's c's
    __shared__ float Gt[2][TR * AA];   // 2 x 8 KB tile double buffer

    const int y    = blockIdx.y;
    const int q    = blockIdx.x;
    const int tid  = threadIdx.x;
    const int w    = tid >> 5;
    const int lane = tid & 31;

    // Labels may be int32 (JAX default) or int64 (x64). Range-check the first
    // 8 int64 interpretations: int32 data aliases high words, blows the range.
    if (q == 0 && y == 0 && tid == 0) {
        int ok = 1;
#pragma unroll
        for (int i = 0; i < 8; i++) {
            long long v = labels[i];
            if (v < 0 || v >= CC) ok = 0;
        }
        g_lab64 = ok;
    }

    // Build Dq = W[q*16 + r][:] - W[y][:]   (vectorized, coalesced)
    const float* wy = W + y * AA;
    for (int idx = tid; idx < CB * (AA / 4); idx += NT) {
        const int r  = idx >> 6;           // / (AA/4)
        const int a4 = (idx & 63) << 2;
        float4 wv = *(const float4*)(W + (q * CB + r) * AA + a4);
        float4 yv = *(const float4*)(wy + a4);
        float4 d;
        d.x = wv.x - yv.x; d.y = wv.y - yv.y;
        d.z = wv.z - yv.z; d.w = wv.w - yv.w;
        *(float4*)(&Dq[r][a4]) = d;
    }

    const float* G = CV + (size_t)y * (AA * AA);

    // Prologue: tile 0 -> buffer 0 (TR*AA = 2048 floats; 4 float4 per thread)
    float4 pf0, pf1, pf2, pf3;
    pf0 = *(const float4*)(G + (0 * NT + tid) * 4);
    pf1 = *(const float4*)(G + (1 * NT + tid) * 4);
    pf2 = *(const float4*)(G + (2 * NT + tid) * 4);
    pf3 = *(const float4*)(G + (3 * NT + tid) * 4);
    *(float4*)(&Gt[0][(0 * NT + tid) * 4]) = pf0;
    *(float4*)(&Gt[0][(1 * NT + tid) * 4]) = pf1;
    *(float4*)(&Gt[0][(2 * NT + tid) * 4]) = pf2;
    *(float4*)(&Gt[0][(3 * NT + tid) * 4]) = pf3;
    __syncthreads();

    const int c0 = w * 4;   // Dq row base for this warp
    float acc[4][8];
#pragma unroll
    for (int ci = 0; ci < 4; ci++)
#pragma unroll
        for (int k = 0; k < 8; k++) acc[ci][k] = 0.f;

    const int b0 = lane * 4;          // first 4 b-cols
    const int b1 = 128 + lane * 4;    // second 4 b-cols

#pragma unroll 1
    for (int t = 0; t < AA / TR; t++) {
        if (t + 1 < AA / TR) {        // prefetch next tile to registers
            const float* Gn = G + (size_t)(t + 1) * (TR * AA);
            pf0 = *(const float4*)(Gn + (0 * NT + tid) * 4);
            pf1 = *(const float4*)(Gn + (1 * NT + tid) * 4);
            pf2 = *(const float4*)(Gn + (2 * NT + tid) * 4);
            pf3 = *(const float4*)(Gn + (3 * NT + tid) * 4);
        }
        const float* buf = Gt[t & 1];
        const int abase = t * TR;
#pragma unroll
        for (int rr = 0; rr < TR; rr += 4) {
            float4 u[4];
#pragma unroll
            for (int ci = 0; ci < 4; ci++)     // warp-broadcast loads
                u[ci] = *(const float4*)(&Dq[c0 + ci][abase + rr]);
#pragma unroll
            for (int e = 0; e < 4; e++) {
                const int r = rr + e;
                float4 g0 = *(const float4*)(buf + r * AA + b0);
                float4 g1 = *(const float4*)(buf + r * AA + b1);
#pragma unroll
                for (int ci = 0; ci < 4; ci++) {
                    const float uu = (e == 0) ? u[ci].x :
                                     (e == 1) ? u[ci].y :
                                     (e == 2) ? u[ci].z : u[ci].w;
                    acc[ci][0] = fmaf(uu, g0.x, acc[ci][0]);
                    acc[ci][1] = fmaf(uu, g0.y, acc[ci][1]);
                    acc[ci][2] = fmaf(uu, g0.z, acc[ci][2]);
                    acc[ci][3] = fmaf(uu, g0.w, acc[ci][3]);
                    acc[ci][4] = fmaf(uu, g1.x, acc[ci][4]);
                    acc[ci][5] = fmaf(uu, g1.y, acc[ci][5]);
                    acc[ci][6] = fmaf(uu, g1.z, acc[ci][6]);
                    acc[ci][7] = fmaf(uu, g1.w, acc[ci][7]);
                }
            }
        }
        if (t + 1 < AA / TR) {
            __syncthreads();   // all readers done with the buffer we overwrite
            float* nbuf = Gt[(t + 1) & 1];
            *(float4*)(&nbuf[(0 * NT + tid) * 4]) = pf0;
            *(float4*)(&nbuf[(1 * NT + tid) * 4]) = pf1;
            *(float4*)(&nbuf[(2 * NT + tid) * 4]) = pf2;
            *(float4*)(&nbuf[(3 * NT + tid) * 4]) = pf3;
            __syncthreads();
        }
    }

    // Epilogue: S = sum_b t[c,b] * D[c,b]; warp-reduce, lane 0 writes
#pragma unroll
    for (int ci = 0; ci < 4; ci++) {
        float4 d0 = *(const float4*)(&Dq[c0 + ci][b0]);
        float4 d1 = *(const float4*)(&Dq[c0 + ci][b1]);
        float p = acc[ci][0] * d0.x + acc[ci][1] * d0.y
                + acc[ci][2] * d0.z + acc[ci][3] * d0.w
                + acc[ci][4] * d1.x + acc[ci][5] * d1.y
                + acc[ci][6] * d1.z + acc[ci][7] * d1.w;
#pragma unroll
        for (int off = 16; off; off >>= 1)
            p += __shfl_xor_sync(0xffffffffu, p, off);
        if (lane == 0)
            g_S[y * CC + q * CB + c0 + ci] = p;
    }
}

// ---------------------------------------------------------------------------
// Per-row softmax cross-entropy + fused final mean (threadfence reduction).
// 64 blocks x 512 threads; each warp handles 4 consecutive rows.
// ---------------------------------------------------------------------------
__global__ __launch_bounds__(512) void k_loss(
        const float* __restrict__ pred, const void* __restrict__ labels,
        const float* __restrict__ Lam, float* __restrict__ out, int n_total) {
    const int w    = threadIdx.x >> 5;     // 0..15
    const int lane = threadIdx.x & 31;
    __shared__ float ws[16];

    const int   lab64 = g_lab64;
    const float lam   = 0.5f * __ldg(Lam);

    float wsum = 0.f;
#pragma unroll
    for (int rr = 0; rr < 4; rr++) {
        const int n = (blockIdx.x * 16 + w) * 4 + rr;
        if (n >= n_total) break;
        const int y = lab64 ? (int)((const long long*)labels)[n]
                            : ((const int*)labels)[n];
        const float* p = pred + (size_t)n * CC;
        const int c2 = lane + 32;

        float a1 = p[lane] + lam * g_S[y * CC + lane];
        float a2 = p[c2]   + lam * g_S[y * CC + c2];

        float m = fmaxf(a1, a2);
#pragma unroll
        for (int off = 16; off; off >>= 1)
            m = fmaxf(m, __shfl_xor_sync(0xffffffffu, m, off));
        float e = __expf(a1 - m) + __expf(a2 - m);
#pragma unroll
        for (int off = 16; off; off >>= 1)
            e += __shfl_xor_sync(0xffffffffu, e, off);
        float ay = (lane == y) ? a1 : ((c2 == y) ? a2 : -3.4e38f);
#pragma unroll
        for (int off = 16; off; off >>= 1)
            ay = fmaxf(ay, __shfl_xor_sync(0xffffffffu, ay, off));
        wsum += m + __logf(e) - ay;
    }

    if (lane == 0) ws[w] = wsum;
    __syncthreads();
    if (threadIdx.x == 0) {
        float s = 0.f;
#pragma unroll
        for (int i = 0; i < 16; i++) s += ws[i];
        g_blockSums[blockIdx.x] = s;
        __threadfence();
        int old = atomicAdd(&g_count, 1);
        ws[0] = (old == gridDim.x - 1) ? 1.f : 0.f;
    }
    __syncthreads();

    // Last block: deterministic fixed-tree sum of 64 partials, then reset.
    if (ws[0] != 0.f && w == 0) {
        float v = g_blockSums[lane] + g_blockSums[lane + 32];
#pragma unroll
        for (int off = 16; off; off >>= 1)
            v += __shfl_xor_sync(0xffffffffu, v, off);
        if (lane == 0) {
            out[0] = v / (float)n_total;
            g_count = 0;    // reset for next graph replay
        }
    }
}

// ---------------------------------------------------------------------------
// Inputs (metadata order): fc_weight[C,A] f32, features (unused), pred[N,C] f32,
// labels[N] i32/i64, Lambda[1] f32, covariance_sample[C,A,A] f32.
// ---------------------------------------------------------------------------
extern "C" void kernel_launch(void* const* d_in, const int* in_sizes, int n_in,
                              void* d_out, int out_size) {
    const float* W      = (const float*)d_in[0];
    const float* pred   = (const float*)d_in[2];
    const void*  labels = d_in[3];
    const float* Lam    = (const float*)d_in[4];
    const float* CV     = (const float*)d_in[5];
    const int n_total   = in_sizes[2] / CC;   // 4096

    k_quad<<<dim3(CSPLIT, CC), NT>>>(W, CV, (const long long*)labels);
    k_loss<<<LOSS_NB, 512>>>(pred, labels, Lam, (float*)d_out, n_total);
}

// round 4
// speedup vs baseline: 1.0703x; 1.0571x over previous
#include <cuda_runtime.h>

// Shapes fixed by the dataset
#define CC  64      // classes
#define AA  256     // feature dim
#define CSPLIT 4    // c-slices per y  -> grid 4*64 = 256 blocks
#define CB  16      // classes per block
#define NT  128     // threads per block (4 warps)
#define TR  8       // a-rows per G tile
#define NB  (CSPLIT * CC)   // 256 blocks
#define NROW 4096

// Fixed-slot scratch (deterministic, no allocation)
__device__ float g_S[CC * CC];            // S[y][c]
__device__ float g_blockSums[NB];
__device__ unsigned g_sync  = 0;          // epoch grid-sync counter (monotonic)
__device__ unsigned g_done  = 0;          // epoch final-reduction counter
__device__ int   g_lab64;

// ---------------------------------------------------------------------------
// Single fused kernel:
//   Phase 1: S[y,c] = (w_c - w_y)^T G_y (w_c - w_y)  (256 blocks, FMA-bound)
//   epoch grid-sync (all 256 blocks co-resident: 32KB smem, 128 thr)
//   Phase 2: softmax-CE over 16 rows per block + fence-counter final mean
// ---------------------------------------------------------------------------
__global__ __launch_bounds__(NT) void k_fused(
        const float* __restrict__ W, const float* __restrict__ CV,
        const float* __restrict__ pred, const void* __restrict__ labels,
        const float* __restrict__ Lam, float* __restrict__ out) {
    __shared__ float Dq[CB][AA];       // 16 KB: D rows for this block's c's
    __shared__ float Gt[2][TR * AA];   // 2 x 8 KB tile double buffer
    __shared__ float ws[4];
    __shared__ unsigned s_flag;

    const int y    = blockIdx.y;
    const int q    = blockIdx.x;
    const int tid  = threadIdx.x;
    const int w    = tid >> 5;
    const int lane = tid & 31;
    const int bid  = y * CSPLIT + q;

    // Labels may be int32 (JAX default) or int64 (x64). Range-check the first
    // 8 int64 interpretations: int32 data aliases high words, blows the range.
    if (bid == 0 && tid == 0) {
        int ok = 1;
#pragma unroll
        for (int i = 0; i < 8; i++) {
            long long v = ((const long long*)labels)[i];
            if (v < 0 || v >= CC) ok = 0;
        }
        g_lab64 = ok;
    }

    // ---- Phase 1: quadratic forms -------------------------------------
    const float* wy = W + y * AA;
    for (int idx = tid; idx < CB * (AA / 4); idx += NT) {
        const int r  = idx >> 6;           // / (AA/4)
        const int a4 = (idx & 63) << 2;
        float4 wv = *(const float4*)(W + (q * CB + r) * AA + a4);
        float4 yv = *(const float4*)(wy + a4);
        float4 d;
        d.x = wv.x - yv.x; d.y = wv.y - yv.y;
        d.z = wv.z - yv.z; d.w = wv.w - yv.w;
        *(float4*)(&Dq[r][a4]) = d;
    }

    const float* G = CV + (size_t)y * (AA * AA);

    float4 pf0, pf1, pf2, pf3;
    pf0 = *(const float4*)(G + (0 * NT + tid) * 4);
    pf1 = *(const float4*)(G + (1 * NT + tid) * 4);
    pf2 = *(const float4*)(G + (2 * NT + tid) * 4);
    pf3 = *(const float4*)(G + (3 * NT + tid) * 4);
    *(float4*)(&Gt[0][(0 * NT + tid) * 4]) = pf0;
    *(float4*)(&Gt[0][(1 * NT + tid) * 4]) = pf1;
    *(float4*)(&Gt[0][(2 * NT + tid) * 4]) = pf2;
    *(float4*)(&Gt[0][(3 * NT + tid) * 4]) = pf3;
    __syncthreads();

    const int c0 = w * 4;
    float acc[4][8];
#pragma unroll
    for (int ci = 0; ci < 4; ci++)
#pragma unroll
        for (int k = 0; k < 8; k++) acc[ci][k] = 0.f;

    const int b0 = lane * 4;
    const int b1 = 128 + lane * 4;

#pragma unroll 1
    for (int t = 0; t < AA / TR; t++) {
        if (t + 1 < AA / TR) {        // prefetch next tile to registers
            const float* Gn = G + (size_t)(t + 1) * (TR * AA);
            pf0 = *(const float4*)(Gn + (0 * NT + tid) * 4);
            pf1 = *(const float4*)(Gn + (1 * NT + tid) * 4);
            pf2 = *(const float4*)(Gn + (2 * NT + tid) * 4);
            pf3 = *(const float4*)(Gn + (3 * NT + tid) * 4);
        }
        const float* buf = Gt[t & 1];
        const int abase = t * TR;
#pragma unroll
        for (int rr = 0; rr < TR; rr += 4) {
            float4 u[4];
#pragma unroll
            for (int ci = 0; ci < 4; ci++)     // warp-broadcast loads
                u[ci] = *(const float4*)(&Dq[c0 + ci][abase + rr]);
#pragma unroll
            for (int e = 0; e < 4; e++) {
                const int r = rr + e;
                float4 g0 = *(const float4*)(buf + r * AA + b0);
                float4 g1 = *(const float4*)(buf + r * AA + b1);
#pragma unroll
                for (int ci = 0; ci < 4; ci++) {
                    const float uu = (e == 0) ? u[ci].x :
                                     (e == 1) ? u[ci].y :
                                     (e == 2) ? u[ci].z : u[ci].w;
                    acc[ci][0] = fmaf(uu, g0.x, acc[ci][0]);
                    acc[ci][1] = fmaf(uu, g0.y, acc[ci][1]);
                    acc[ci][2] = fmaf(uu, g0.z, acc[ci][2]);
                    acc[ci][3] = fmaf(uu, g0.w, acc[ci][3]);
                    acc[ci][4] = fmaf(uu, g1.x, acc[ci][4]);
                    acc[ci][5] = fmaf(uu, g1.y, acc[ci][5]);
                    acc[ci][6] = fmaf(uu, g1.z, acc[ci][6]);
                    acc[ci][7] = fmaf(uu, g1.w, acc[ci][7]);
                }
            }
        }
        if (t + 1 < AA / TR) {
            __syncthreads();
            float* nbuf = Gt[(t + 1) & 1];
            *(float4*)(&nbuf[(0 * NT + tid) * 4]) = pf0;
            *(float4*)(&nbuf[(1 * NT + tid) * 4]) = pf1;
            *(float4*)(&nbuf[(2 * NT + tid) * 4]) = pf2;
            *(float4*)(&nbuf[(3 * NT + tid) * 4]) = pf3;
            __syncthreads();
        }
    }

#pragma unroll
    for (int ci = 0; ci < 4; ci++) {
        float4 d0 = *(const float4*)(&Dq[c0 + ci][b0]);
        float4 d1 = *(const float4*)(&Dq[c0 + ci][b1]);
        float p = acc[ci][0] * d0.x + acc[ci][1] * d0.y
                + acc[ci][2] * d0.z + acc[ci][3] * d0.w
                + acc[ci][4] * d1.x + acc[ci][5] * d1.y
                + acc[ci][6] * d1.z + acc[ci][7] * d1.w;
#pragma unroll
        for (int off = 16; off; off >>= 1)
            p += __shfl_xor_sync(0xffffffffu, p, off);
        if (lane == 0)
            g_S[y * CC + q * CB + c0 + ci] = p;
    }

    // ---- Epoch grid-sync (monotonic counter; no reset, graph-replay safe).
    // All 256 blocks are co-resident (1 wave), so polling cannot deadlock.
    __syncthreads();
    if (tid == 0) {
        __threadfence();
        unsigned old = atomicAdd(&g_sync, 1u);
        unsigned target = (old / NB + 1u) * NB;
        while (*(volatile unsigned*)&g_sync < target) { }
        __threadfence();
    }
    __syncthreads();

    // ---- Phase 2: softmax-CE over rows [bid*16, bid*16+16) -------------
    const int   lab64 = g_lab64;
    const float lam   = 0.5f * __ldg(Lam);

    float wsum = 0.f;
#pragma unroll
    for (int rr = 0; rr < 4; rr++) {
        const int n = bid * 16 + w * 4 + rr;
        const int yl = lab64 ? (int)((const long long*)labels)[n]
                             : ((const int*)labels)[n];
        const float* p = pred + (size_t)n * CC;
        const int c2 = lane + 32;

        float a1 = p[lane] + lam * g_S[yl * CC + lane];
        float a2 = p[c2]   + lam * g_S[yl * CC + c2];

        float m = fmaxf(a1, a2);
#pragma unroll
        for (int off = 16; off; off >>= 1)
            m = fmaxf(m, __shfl_xor_sync(0xffffffffu, m, off));
        float e = __expf(a1 - m) + __expf(a2 - m);
#pragma unroll
        for (int off = 16; off; off >>= 1)
            e += __shfl_xor_sync(0xffffffffu, e, off);
        // y is warp-uniform: fetch a_y with a single shuffle, no reduction
        float ay = __shfl_sync(0xffffffffu, (yl < 32) ? a1 : a2, yl & 31);
        wsum += m + __logf(e) - ay;
    }

    if (lane == 0) ws[w] = wsum;
    __syncthreads();
    if (tid == 0) {
        g_blockSums[bid] = ws[0] + ws[1] + ws[2] + ws[3];
        __threadfence();
        unsigned old = atomicAdd(&g_done, 1u);
        s_flag = ((old % NB) == NB - 1u) ? 1u : 0u;
    }
    __syncthreads();

    // Last-arriving block: deterministic fixed-order sum of 256 partials
    if (s_flag && w == 0) {
        __threadfence();
        float v = 0.f;
#pragma unroll
        for (int k = 0; k < NB / 32; k++)
            v += g_blockSums[k * 32 + lane];
#pragma unroll
        for (int off = 16; off; off >>= 1)
            v += __shfl_xor_sync(0xffffffffu, v, off);
        if (lane == 0)
            out[0] = v / (float)NROW;
    }
}

// ---------------------------------------------------------------------------
// Inputs (metadata order): fc_weight[C,A] f32, features (unused), pred[N,C] f32,
// labels[N] i32/i64, Lambda[1] f32, covariance_sample[C,A,A] f32.
// ---------------------------------------------------------------------------
extern "C" void kernel_launch(void* const* d_in, const int* in_sizes, int n_in,
                              void* d_out, int out_size) {
    const float* W      = (const float*)d_in[0];
    const float* pred   = (const float*)d_in[2];
    const void*  labels = d_in[3];
    const float* Lam    = (const float*)d_in[4];
    const float* CV     = (const float*)d_in[5];

    k_fused<<<dim3(CSPLIT, CC), NT>>>(W, CV, pred, labels, Lam, (float*)d_out);
}